// round 13
// baseline (speedup 1.0000x reference)
#include <cuda_runtime.h>
#include <cstdint>

#define B_ 64
#define T_ 2048
#define I_ 512
#define H_ 1024
#define MTOT (B_ * T_)
#define BSTRIDE ((size_t)T_ * H_)   // stride between batch rows in out
#define NBLK 128                    // persistent grid: 16 n-tiles x 8 k-slabs

// Scratch: Uw transposed to [k][n] (R4-validated).
__device__ float g_UwT[H_ * H_];
// Per-n-tile arrival counters, one 128B line each (16 tiles x 32 u32).
__device__ unsigned g_flags[16 * 32];

// ---------------------------------------------------------------------------
// packed-fp32 helpers (sm_103a FFMA2 via PTX fma.rn.f32x2; exact IEEE RN
// per lane -> identical numerics to scalar FFMA in the same order)
// ---------------------------------------------------------------------------
__device__ __forceinline__ unsigned long long dup2(float x) {
    unsigned long long r; unsigned u = __float_as_uint(x);
    asm("mov.b64 %0, {%1, %2};" : "=l"(r) : "r"(u), "r"(u));
    return r;
}
__device__ __forceinline__ void fma2(unsigned long long& d,
                                     unsigned long long a, unsigned long long b) {
    asm("fma.rn.f32x2 %0, %1, %2, %0;" : "+l"(d) : "l"(a), "l"(b));
}
__device__ __forceinline__ float2 unpk(unsigned long long v) {
    unsigned lo, hi;
    asm("mov.b64 {%0, %1}, %2;" : "=r"(lo), "=r"(hi) : "l"(v));
    return make_float2(__uint_as_float(lo), __uint_as_float(hi));
}

// ---------------------------------------------------------------------------
// init: zero the per-tile flag counters (must run every replay)
// ---------------------------------------------------------------------------
__global__ void init_kernel() {
    if (threadIdx.x < 16 * 32) g_flags[threadIdx.x] = 0u;
}

// ---------------------------------------------------------------------------
// Transpose Uw[n][k] -> g_UwT[k][n]. (R4-validated)
// ---------------------------------------------------------------------------
__global__ __launch_bounds__(256) void uw_transpose_kernel(const float* __restrict__ Uw) {
    __shared__ float tile[32][33];
    const int bx = blockIdx.x * 32;
    const int by = blockIdx.y * 32;
    const int tx = threadIdx.x & 31;
    const int tw = threadIdx.x >> 5;
#pragma unroll
    for (int r = 0; r < 32; r += 8)
        tile[tw + r][tx] = Uw[(size_t)(by + tw + r) * H_ + bx + tx];
    __syncthreads();
#pragma unroll
    for (int r = 0; r < 32; r += 8)
        g_UwT[(size_t)(bx + tw + r) * H_ + by + tx] = tile[tx][tw + r];
}

// ---------------------------------------------------------------------------
// Projection (fp32 FFMA2) — R12-validated. out = x@W^T + Ub + b.
// ---------------------------------------------------------------------------
__global__ __launch_bounds__(256) void proj_kernel(
    const float* __restrict__ x, const float* __restrict__ W,
    const float* __restrict__ Ub, const float* __restrict__ bvec,
    float* __restrict__ out)
{
    __shared__ float As[16][128];
    __shared__ float Bs[16][128];
    const int tid = threadIdx.x;
    const int m0 = blockIdx.y * 128;
    const int n0 = blockIdx.x * 128;
    const int ty = tid >> 4;   // 0..15
    const int tx = tid & 15;   // 0..15

    unsigned long long acc[8][4];
#pragma unroll
    for (int i = 0; i < 8; i++)
#pragma unroll
        for (int j = 0; j < 4; j++) acc[i][j] = 0ull;

    for (int kb = 0; kb < I_; kb += 16) {
#pragma unroll
        for (int l = 0; l < 2; l++) {
            int idx = tid + l * 256;
            int row = idx >> 2;
            int c4  = (idx & 3) << 2;
            float4 av = *(const float4*)(x + (size_t)(m0 + row) * I_ + kb + c4);
            As[c4 + 0][row] = av.x; As[c4 + 1][row] = av.y;
            As[c4 + 2][row] = av.z; As[c4 + 3][row] = av.w;
            float4 wv = *(const float4*)(W + (size_t)(n0 + row) * I_ + kb + c4);
            Bs[c4 + 0][row] = wv.x; Bs[c4 + 1][row] = wv.y;
            Bs[c4 + 2][row] = wv.z; Bs[c4 + 3][row] = wv.w;
        }
        __syncthreads();
#pragma unroll
        for (int k = 0; k < 16; k++) {
            float4 a0 = *(const float4*)&As[k][ty * 8];
            float4 a1 = *(const float4*)&As[k][ty * 8 + 4];
            ulonglong2 b01 = *(const ulonglong2*)&Bs[k][tx * 8];
            ulonglong2 b23 = *(const ulonglong2*)&Bs[k][tx * 8 + 4];
            unsigned long long ad[8];
            ad[0] = dup2(a0.x); ad[1] = dup2(a0.y); ad[2] = dup2(a0.z); ad[3] = dup2(a0.w);
            ad[4] = dup2(a1.x); ad[5] = dup2(a1.y); ad[6] = dup2(a1.z); ad[7] = dup2(a1.w);
#pragma unroll
            for (int i = 0; i < 8; i++) {
                fma2(acc[i][0], ad[i], b01.x);
                fma2(acc[i][1], ad[i], b01.y);
                fma2(acc[i][2], ad[i], b23.x);
                fma2(acc[i][3], ad[i], b23.y);
            }
        }
        __syncthreads();
    }

    float ubb[8];
#pragma unroll
    for (int j = 0; j < 8; j++) {
        int n = n0 + tx * 8 + j;
        ubb[j] = Ub[n] + bvec[n];
    }
#pragma unroll
    for (int i = 0; i < 8; i++) {
        float2 p0 = unpk(acc[i][0]);
        float2 p1 = unpk(acc[i][1]);
        float2 p2 = unpk(acc[i][2]);
        float2 p3 = unpk(acc[i][3]);
        float* dst = out + (size_t)(m0 + ty * 8 + i) * H_ + n0 + tx * 8;
        float4 v0 = make_float4(p0.x + ubb[0], p0.y + ubb[1],
                                p1.x + ubb[2], p1.y + ubb[3]);
        float4 v1 = make_float4(p2.x + ubb[4], p2.y + ubb[5],
                                p3.x + ubb[6], p3.y + ubb[7]);
        *(float4*)dst       = v0;
        *(float4*)(dst + 4) = v1;
    }
}

// ---------------------------------------------------------------------------
// Persistent fp32 recurrence (FFMA2) — R12-validated compute/staging/RED,
// with the global lockstep barrier replaced by per-n-tile wavefront flags:
//   producer (n-tile j, k-slab s) arrives at flag[j] after its REDs are
//   fenced; consumer waits only on flag[2s] and flag[2s+1] >= t*8.
// ---------------------------------------------------------------------------
__global__ __launch_bounds__(256) void rnn_persistent_kernel(float* __restrict__ out)
{
    __shared__ float Ss[64][132];    // [b][k-slab], padded
    __shared__ float Us[128][64];    // [k-slab][n-tile]
    const int tid = threadIdx.x;
    const int bid = blockIdx.x;
    const int jt  = bid & 15;        // my n-tile (arrival counter index)
    const int ks  = bid >> 4;        // my k-slab index
    const int n0 = jt * 64;
    const int k0 = ks * 128;
    const int j0 = ks * 2;           // producer tiles covering [k0, k0+128)
    const int j1 = j0 + 1;
    const int ty = tid >> 4;         // 0..15 -> b-quad
    const int tx = tid & 15;         // 0..15 -> n-quad

    // Preload UwT slab (128 x 64 floats) once.
#pragma unroll
    for (int l = 0; l < 8; l++) {
        int idx = tid + l * 256;
        int r  = idx >> 4;
        int c4 = (idx & 15) << 2;
        *(float4*)&Us[r][c4] =
            *(const float4*)(g_UwT + (size_t)(k0 + r) * H_ + n0 + c4);
    }
    __syncthreads();

    for (int t = 1; t < T_; t++) {
        const float* prev = out + (size_t)(t - 1) * H_ + k0;
#pragma unroll
        for (int l = 0; l < 8; l++) {
            int idx = tid + l * 256;
            int b   = idx >> 5;
            int c4  = (idx & 31) << 2;
            *(float4*)&Ss[b][c4] =
                *(const float4*)(prev + (size_t)b * BSTRIDE + c4);
        }
        __syncthreads();

        unsigned long long acc[4][2];
#pragma unroll
        for (int i = 0; i < 4; i++) { acc[i][0] = 0ull; acc[i][1] = 0ull; }

#pragma unroll 8
        for (int k = 0; k < 128; k += 2) {
            ulonglong2 bb0 = *(const ulonglong2*)&Us[k][tx * 4];
            ulonglong2 bb1 = *(const ulonglong2*)&Us[k + 1][tx * 4];
            float2 a0 = *(const float2*)&Ss[ty * 4 + 0][k];
            float2 a1 = *(const float2*)&Ss[ty * 4 + 1][k];
            float2 a2 = *(const float2*)&Ss[ty * 4 + 2][k];
            float2 a3 = *(const float2*)&Ss[ty * 4 + 3][k];
            unsigned long long d;
            d = dup2(a0.x); fma2(acc[0][0], d, bb0.x); fma2(acc[0][1], d, bb0.y);
            d = dup2(a0.y); fma2(acc[0][0], d, bb1.x); fma2(acc[0][1], d, bb1.y);
            d = dup2(a1.x); fma2(acc[1][0], d, bb0.x); fma2(acc[1][1], d, bb0.y);
            d = dup2(a1.y); fma2(acc[1][0], d, bb1.x); fma2(acc[1][1], d, bb1.y);
            d = dup2(a2.x); fma2(acc[2][0], d, bb0.x); fma2(acc[2][1], d, bb0.y);
            d = dup2(a2.y); fma2(acc[2][0], d, bb1.x); fma2(acc[2][1], d, bb1.y);
            d = dup2(a3.x); fma2(acc[3][0], d, bb0.x); fma2(acc[3][1], d, bb0.y);
            d = dup2(a3.y); fma2(acc[3][0], d, bb1.x); fma2(acc[3][1], d, bb1.y);
        }

#pragma unroll
        for (int i = 0; i < 4; i++) {
            float2 p0 = unpk(acc[i][0]);
            float2 p1 = unpk(acc[i][1]);
            float* dst = out + (size_t)(ty * 4 + i) * BSTRIDE
                             + (size_t)t * H_ + n0 + tx * 4;
            asm volatile("red.global.add.v4.f32 [%0], {%1,%2,%3,%4};"
                         :: "l"(dst), "f"(p0.x), "f"(p0.y), "f"(p1.x), "f"(p1.y)
                         : "memory");
        }

        if (t < T_ - 1) {
            __threadfence();       // each thread publishes its own REDs gpu-wide
            __syncthreads();       // all 256 threads' REDs fenced before arrival
            if (tid == 0) {
                // arrive at my n-tile's counter (release: publish after fences)
                asm volatile("red.release.gpu.global.add.u32 [%0], %1;"
                             :: "l"(g_flags + jt * 32), "r"(1u) : "memory");
                // wait for producer tile j0 of my k-slab
                unsigned target = (unsigned)t * 8u, v;
                do {
                    asm volatile("ld.acquire.gpu.global.u32 %0, [%1];"
                                 : "=r"(v) : "l"(g_flags + j0 * 32) : "memory");
                } while (v < target);
            } else if (tid == 32) {
                // second warp polls producer tile j1 in parallel
                unsigned target = (unsigned)t * 8u, v;
                do {
                    asm volatile("ld.acquire.gpu.global.u32 %0, [%1];"
                                 : "=r"(v) : "l"(g_flags + j1 * 32) : "memory");
                } while (v < target);
            }
            __syncthreads();       // broadcast both waits; guards smem reuse
        }
    }
}

// ---------------------------------------------------------------------------
extern "C" void kernel_launch(void* const* d_in, const int* in_sizes, int n_in,
                              void* d_out, int out_size) {
    (void)in_sizes; (void)n_in; (void)out_size;
    const float* x   = (const float*)d_in[0];
    const float* W   = (const float*)d_in[1];
    const float* Uw  = (const float*)d_in[2];
    const float* Ub  = (const float*)d_in[3];
    const float* bv  = (const float*)d_in[4];
    float* out = (float*)d_out;

    // 1) zero flags + transpose Uw -> g_UwT
    init_kernel<<<1, 512>>>();
    uw_transpose_kernel<<<dim3(H_ / 32, H_ / 32), 256>>>(Uw);

    // 2) wx = x @ W^T + Ub + b   (fp32 FFMA2)
    proj_kernel<<<dim3(H_ / 128, MTOT / 128), 256>>>(x, W, Ub, bv, out);

    // 3) all 2047 recurrence steps, fp32 FFMA2 persistent kernel,
    //    wavefront per-tile flags instead of a global lockstep barrier
    rnn_persistent_kernel<<<NBLK, 256>>>(out);
}